// round 2
// baseline (speedup 1.0000x reference)
#include <cuda_runtime.h>
#include <math.h>
#include <stdint.h>

#define B_  256
#define T_  512
#define E_  128
#define H_  256
#define G_  768   // 3*H
#define V1  65
#define MB  4     // batch rows per recurrence CTA
#define KC_ 64    // FC1 K-split chunks

// ---------------- scratch (static device globals; no allocation) ----------------
__device__ float g_embproj[2][V1][G_];            // L0 input proj per token (bias folded)
__device__ float g_whh0T[2][H_][G_];              // w_hh_l0 transposed [d][k][g]
__device__ float g_whh1T[2][H_][G_];
__device__ float g_wih1T[2][2 * H_][G_];          // w_ih_l1 transposed [d][c][g]
__device__ float g_h1[T_][B_][2 * H_];            // layer0 output [t][b][c]
__device__ float g_xp1[2][(size_t)T_ * B_][G_];   // layer1 input proj (bias folded)
__device__ float g_h2[T_][B_][2 * H_];            // layer1 output [t][b][c]
__device__ float g_fc1p[KC_][B_][128];            // FC1 K-split partials
__device__ float g_fc1[B_][128];

// ---------------- prep: embedding projection for layer 0 ----------------
__global__ void k_embproj(const float* __restrict__ emb,
                          const float* __restrict__ w_ih0,
                          const float* __restrict__ b_ih0) {
    __shared__ float es[E_];
    int d = blockIdx.x / V1;
    int v = blockIdx.x % V1;
    int g = threadIdx.x;                   // 0..767
    if (g < E_) es[g] = emb[v * E_ + g];
    __syncthreads();
    const float* w = w_ih0 + ((size_t)d * G_ + g) * E_;
    float acc = b_ih0[d * G_ + g];
#pragma unroll 4
    for (int e = 0; e < E_; e++) acc = fmaf(es[e], w[e], acc);
    g_embproj[d][v][g] = acc;
}

// ---------------- prep: weight transposes [2][G][K] -> [2][K][G] ----------------
__global__ void k_transpose(const float* __restrict__ in, int K, int which) {
    float* out = (which == 0) ? &g_whh0T[0][0][0]
               : (which == 1) ? &g_whh1T[0][0][0]
                              : &g_wih1T[0][0][0];
    size_t total = (size_t)2 * G_ * K;
    for (size_t i = (size_t)blockIdx.x * blockDim.x + threadIdx.x; i < total;
         i += (size_t)gridDim.x * blockDim.x) {
        int k = (int)(i % K);
        size_t r = i / K;
        int g = (int)(r % G_);
        int d = (int)(r / G_);
        out[((size_t)d * K + k) * G_ + g] = in[i];
    }
}

__device__ __forceinline__ float sigmoidf_(float x) { return 1.0f / (1.0f + expf(-x)); }

// ---------------- GRU recurrence (one CTA owns MB batch rows of one direction) ----
// grid: 2 * (B_/MB) blocks, 256 threads. Thread j owns hidden unit j (gates r,z,n).
template <int LAYER>
__global__ void k_rec(const int* __restrict__ inputs, const float* __restrict__ bhh) {
    const int nb = B_ / MB;                 // 64
    int d  = blockIdx.x / nb;
    int b0 = (blockIdx.x % nb) * MB;
    int j  = threadIdx.x;                   // 0..255

    __shared__ __align__(16) float h_s[MB][H_];
    __shared__ int tok_s[MB];

#pragma unroll
    for (int m = 0; m < MB; m++) h_s[m][j] = 0.0f;

    const float* whhT = (LAYER == 0) ? &g_whh0T[d][0][0] : &g_whh1T[d][0][0]; // [k][G_]
    float bR = bhh[d * G_ + j];
    float bZ = bhh[d * G_ + H_ + j];
    float bN = bhh[d * G_ + 2 * H_ + j];
    __syncthreads();

    for (int s = 0; s < T_; s++) {
        int t = (d == 0) ? s : (T_ - 1 - s);
        if (LAYER == 0) {
            if (j < MB) tok_s[j] = inputs[(size_t)(b0 + j) * T_ + t];
        }
        __syncthreads();   // tok ready; previous h_s writes visible

        float xr[MB], xz[MB], xn[MB];
#pragma unroll
        for (int m = 0; m < MB; m++) {
            const float* xp = (LAYER == 0)
                ? &g_embproj[d][tok_s[m]][0]
                : &g_xp1[d][(size_t)t * B_ + b0 + m][0];
            xr[m] = xp[j];
            xz[m] = xp[H_ + j];
            xn[m] = xp[2 * H_ + j];
        }

        float aR[MB], aZ[MB], aN[MB];
#pragma unroll
        for (int m = 0; m < MB; m++) { aR[m] = 0.f; aZ[m] = 0.f; aN[m] = 0.f; }

        const float* w = whhT;
        for (int k = 0; k < H_; k += 4) {
            float4 hv4[MB];
#pragma unroll
            for (int m = 0; m < MB; m++)
                hv4[m] = *reinterpret_cast<const float4*>(&h_s[m][k]);
#pragma unroll
            for (int kk = 0; kk < 4; kk++) {
                float wr = w[j];
                float wz = w[H_ + j];
                float wn = w[2 * H_ + j];
#pragma unroll
                for (int m = 0; m < MB; m++) {
                    float hv = reinterpret_cast<const float*>(&hv4[m])[kk];
                    aR[m] = fmaf(hv, wr, aR[m]);
                    aZ[m] = fmaf(hv, wz, aZ[m]);
                    aN[m] = fmaf(hv, wn, aN[m]);
                }
                w += G_;
            }
        }

        float hnew[MB];
#pragma unroll
        for (int m = 0; m < MB; m++) {
            float r = sigmoidf_(xr[m] + aR[m] + bR);
            float z = sigmoidf_(xz[m] + aZ[m] + bZ);
            float n = tanhf(xn[m] + r * (aN[m] + bN));
            hnew[m] = (1.0f - z) * n + z * h_s[m][j];
        }
        __syncthreads();   // everyone done reading h_s

        float* outp = (LAYER == 0) ? &g_h1[t][0][0] : &g_h2[t][0][0];
#pragma unroll
        for (int m = 0; m < MB; m++) {
            h_s[m][j] = hnew[m];
            outp[(size_t)(b0 + m) * (2 * H_) + d * H_ + j] = hnew[m];
        }
    }
}

// ---------------- layer-1 input projection GEMM ----------------
// C[d][m][g] = bias + sum_c h1flat[m][c] * wih1T[d][c][g]
// M = T*B = 131072, K = 512, N = 768 per dir. Tile 128x64, BK=16, 256 thr, 4x8/thread.
__global__ void k_xp1(const float* __restrict__ bih1) {
    const int BM = 128, BN = 64, BK = 16;
    int d  = blockIdx.x / 12;
    int n0 = (blockIdx.x % 12) * BN;
    int m0 = blockIdx.y * BM;

    __shared__ float As[BK][BM + 1];
    __shared__ float Bs[BK][BN];

    int tid = threadIdx.x;
    int tmi = tid & 31;     // row lane
    int tni = tid >> 5;     // 0..7 col group

    const float* A  = &g_h1[0][0][0];          // [131072][512]
    const float* Bm = &g_wih1T[d][0][0];       // [512][768]

    float acc[4][8];
#pragma unroll
    for (int i = 0; i < 4; i++)
#pragma unroll
        for (int jj = 0; jj < 8; jj++) acc[i][jj] = 0.f;

    for (int k0 = 0; k0 < 512; k0 += BK) {
#pragma unroll
        for (int i = 0; i < 8; i++) {          // A: 2048 elems
            int idx = tid + i * 256;
            int m = idx >> 4, k = idx & 15;
            As[k][m] = A[(size_t)(m0 + m) * 512 + k0 + k];
        }
#pragma unroll
        for (int i = 0; i < 4; i++) {          // B: 1024 elems
            int idx = tid + i * 256;
            int k = idx >> 6, n = idx & 63;
            Bs[k][n] = Bm[(size_t)(k0 + k) * G_ + n0 + n];
        }
        __syncthreads();
#pragma unroll
        for (int k = 0; k < BK; k++) {
            float ra[4], rb[8];
#pragma unroll
            for (int i = 0; i < 4; i++) ra[i] = As[k][tmi + 32 * i];
#pragma unroll
            for (int jj = 0; jj < 8; jj++) rb[jj] = Bs[k][tni + 8 * jj];
#pragma unroll
            for (int i = 0; i < 4; i++)
#pragma unroll
                for (int jj = 0; jj < 8; jj++) acc[i][jj] = fmaf(ra[i], rb[jj], acc[i][jj]);
        }
        __syncthreads();
    }

    float* C = &g_xp1[d][0][0];
#pragma unroll
    for (int i = 0; i < 4; i++) {
        int m = m0 + tmi + 32 * i;
#pragma unroll
        for (int jj = 0; jj < 8; jj++) {
            int n = n0 + tni + 8 * jj;
            C[(size_t)m * G_ + n] = acc[i][jj] + bih1[d * G_ + n];
        }
    }
}

// ---------------- FC1: C[256,128] over K=262144, K-split into KC_ chunks ----------
// grid (KC_, 2); CTA computes [128 b x 128 j] partial over its 4096-K chunk.
__global__ void k_fc1(const float* __restrict__ W1) {
    const int BK = 16, CH = 262144 / KC_;   // 4096
    int kc = blockIdx.x;
    int b0 = blockIdx.y * 128;

    __shared__ float As[BK][129];   // [k][b]
    __shared__ float Bs[BK][129];   // [k][j]

    int tid = threadIdx.x;
    int tbi = tid & 15;    // b = tbi + 16*i
    int tji = tid >> 4;    // j = tji + 16*jj

    const float* h2 = &g_h2[0][0][0];

    float acc[8][8];
#pragma unroll
    for (int i = 0; i < 8; i++)
#pragma unroll
        for (int jj = 0; jj < 8; jj++) acc[i][jj] = 0.f;

    for (int kk = 0; kk < CH; kk += BK) {
        int kbase = kc * CH + kk;
        int t  = kbase >> 9;
        int c0 = kbase & 511;                 // BK=16 never crosses a 512 boundary
#pragma unroll
        for (int i = 0; i < 8; i++) {         // A: 128b x 16k
            int idx = tid + i * 256;
            int b = idx >> 4, k = idx & 15;
            As[k][b] = h2[((size_t)t * B_ + b0 + b) * 512 + c0 + k];
        }
#pragma unroll
        for (int i = 0; i < 8; i++) {         // B: 128j x 16k
            int idx = tid + i * 256;
            int j = idx >> 4, k = idx & 15;
            Bs[k][j] = W1[(size_t)j * 262144 + kbase + k];
        }
        __syncthreads();
#pragma unroll
        for (int k = 0; k < BK; k++) {
            float ra[8], rb[8];
#pragma unroll
            for (int i = 0; i < 8; i++) ra[i] = As[k][tbi + 16 * i];
#pragma unroll
            for (int jj = 0; jj < 8; jj++) rb[jj] = Bs[k][tji + 16 * jj];
#pragma unroll
            for (int i = 0; i < 8; i++)
#pragma unroll
                for (int jj = 0; jj < 8; jj++) acc[i][jj] = fmaf(ra[i], rb[jj], acc[i][jj]);
        }
        __syncthreads();
    }
#pragma unroll
    for (int i = 0; i < 8; i++)
#pragma unroll
        for (int jj = 0; jj < 8; jj++)
            g_fc1p[kc][b0 + tbi + 16 * i][tji + 16 * jj] = acc[i][jj];
}

__global__ void k_fc1reduce(const float* __restrict__ b1) {
    int idx = blockIdx.x * 256 + threadIdx.x;   // 0..32767
    int b = idx >> 7, jj = idx & 127;
    float s = b1[jj];
#pragma unroll 8
    for (int kc = 0; kc < KC_; kc++) s += g_fc1p[kc][b][jj];
    g_fc1[b][jj] = (s > 0.f) ? s : 0.01f * s;   // leaky_relu
}

__global__ void k_fc2(const float* __restrict__ W2, const float* __restrict__ b2,
                      float* __restrict__ out) {
    int b = threadIdx.x;
    float s = b2[0];
#pragma unroll 8
    for (int j = 0; j < 128; j++) s = fmaf(g_fc1[b][j], W2[j], s);
    out[b] = 1.0f / (1.0f + expf(-s));
}

// ---------------- launch ----------------
extern "C" void kernel_launch(void* const* d_in, const int* in_sizes, int n_in,
                              void* d_out, int out_size) {
    const int*   inputs  = (const int*)  d_in[0];
    const float* emb     = (const float*)d_in[1];
    const float* w_ih_l0 = (const float*)d_in[2];
    const float* w_hh_l0 = (const float*)d_in[3];
    const float* b_ih_l0 = (const float*)d_in[4];
    const float* b_hh_l0 = (const float*)d_in[5];
    const float* w_ih_l1 = (const float*)d_in[6];
    const float* w_hh_l1 = (const float*)d_in[7];
    const float* b_ih_l1 = (const float*)d_in[8];
    const float* b_hh_l1 = (const float*)d_in[9];
    const float* W1      = (const float*)d_in[10];
    const float* b1      = (const float*)d_in[11];
    const float* W2      = (const float*)d_in[12];
    const float* b2      = (const float*)d_in[13];
    float* out = (float*)d_out;

    k_embproj<<<2 * V1, G_>>>(emb, w_ih_l0, b_ih_l0);
    k_transpose<<<256, 256>>>(w_hh_l0, H_, 0);
    k_transpose<<<256, 256>>>(w_hh_l1, H_, 1);
    k_transpose<<<256, 256>>>(w_ih_l1, 2 * H_, 2);

    k_rec<0><<<2 * (B_ / MB), 256>>>(inputs, b_hh_l0);

    k_xp1<<<dim3(24, (T_ * B_) / 128), 256>>>(b_ih_l1);

    k_rec<1><<<2 * (B_ / MB), 256>>>(inputs, b_hh_l1);

    k_fc1<<<dim3(KC_, 2), 256>>>(W1);
    k_fc1reduce<<<128, 256>>>(b1);
    k_fc2<<<1, 256>>>(W2, b2, out);
}

// round 4
// speedup vs baseline: 1.1482x; 1.1482x over previous
#include <cuda_runtime.h>
#include <cuda_bf16.h>
#include <math.h>
#include <stdint.h>

#define B_  256
#define T_  512
#define E_  128
#define H_  256
#define G_  768   // 3*H
#define V1  65
#define MB  4     // batch rows per recurrence CTA
#define KC_ 64    // FC1 K-split chunks

// ---------------- scratch (static device globals; no allocation) ----------------
__device__ float g_embproj[2][V1][G_];
__device__ float g_whh0T[2][H_][G_];
__device__ float g_whh1T[2][H_][G_];
__device__ __align__(16) __nv_bfloat16 g_h1hi[(size_t)T_ * B_ * 512];
__device__ __align__(16) __nv_bfloat16 g_h1lo[(size_t)T_ * B_ * 512];
__device__ __align__(16) __nv_bfloat16 g_wih1hi[2 * G_ * 512];
__device__ __align__(16) __nv_bfloat16 g_wih1lo[2 * G_ * 512];
__device__ float g_xp1[2][(size_t)T_ * B_][G_];
__device__ float g_h2[T_][B_][2 * H_];
__device__ float g_fc1p[KC_][B_][128];
__device__ float g_fc1[B_][128];

__device__ __forceinline__ uint32_t smem_u32(const void* p) {
    uint32_t a;
    asm("{ .reg .u64 t; cvta.to.shared.u64 t, %1; cvt.u32.u64 %0, t; }" : "=r"(a) : "l"(p));
    return a;
}
__device__ __forceinline__ void split_bf16(float x, __nv_bfloat16& hi, __nv_bfloat16& lo) {
    hi = __float2bfloat16_rn(x);
    lo = __float2bfloat16_rn(x - __bfloat162float(hi));
}
__device__ __forceinline__ void mma_bf16(float* c, const uint32_t* a, const uint32_t* b) {
    asm volatile(
        "mma.sync.aligned.m16n8k16.row.col.f32.bf16.bf16.f32 "
        "{%0,%1,%2,%3}, {%4,%5,%6,%7}, {%8,%9}, {%0,%1,%2,%3};"
        : "+f"(c[0]), "+f"(c[1]), "+f"(c[2]), "+f"(c[3])
        : "r"(a[0]), "r"(a[1]), "r"(a[2]), "r"(a[3]), "r"(b[0]), "r"(b[1]));
}

// ---------------- prep: embedding projection for layer 0 ----------------
__global__ void k_embproj(const float* __restrict__ emb,
                          const float* __restrict__ w_ih0,
                          const float* __restrict__ b_ih0) {
    __shared__ float es[E_];
    int d = blockIdx.x / V1;
    int v = blockIdx.x % V1;
    int g = threadIdx.x;
    if (g < E_) es[g] = emb[v * E_ + g];
    __syncthreads();
    const float* w = w_ih0 + ((size_t)d * G_ + g) * E_;
    float acc = b_ih0[d * G_ + g];
#pragma unroll 4
    for (int e = 0; e < E_; e++) acc = fmaf(es[e], w[e], acc);
    g_embproj[d][v][g] = acc;
}

// ---------------- prep: w_hh transposes [2][G][H] -> [2][H][G] ----------------
__global__ void k_transpose(const float* __restrict__ in, int which) {
    float* out = (which == 0) ? &g_whh0T[0][0][0] : &g_whh1T[0][0][0];
    size_t total = (size_t)2 * G_ * H_;
    for (size_t i = (size_t)blockIdx.x * blockDim.x + threadIdx.x; i < total;
         i += (size_t)gridDim.x * blockDim.x) {
        int k = (int)(i % H_);
        size_t r = i / H_;
        int g = (int)(r % G_);
        int d = (int)(r / G_);
        out[((size_t)d * H_ + k) * G_ + g] = in[i];
    }
}

// ---------------- prep: split w_ih_l1 into bf16 hi/lo ----------------
__global__ void k_split_wih1(const float* __restrict__ w) {
    int i = blockIdx.x * 256 + threadIdx.x;   // 786432 elems, grid 3072
    float x = w[i];
    __nv_bfloat16 hi, lo;
    split_bf16(x, hi, lo);
    g_wih1hi[i] = hi;
    g_wih1lo[i] = lo;
}

__device__ __forceinline__ float sigmoidf_(float x) { return 1.0f / (1.0f + expf(-x)); }

// ---------------- GRU recurrence ----------------
template <int LAYER>
__global__ void k_rec(const int* __restrict__ inputs, const float* __restrict__ bhh) {
    const int nb = B_ / MB;
    int d  = blockIdx.x / nb;
    int b0 = (blockIdx.x % nb) * MB;
    int j  = threadIdx.x;

    __shared__ __align__(16) float h_s[MB][H_];
    __shared__ int tok_s[MB];

#pragma unroll
    for (int m = 0; m < MB; m++) h_s[m][j] = 0.0f;

    const float* whhT = (LAYER == 0) ? &g_whh0T[d][0][0] : &g_whh1T[d][0][0];
    float bR = bhh[d * G_ + j];
    float bZ = bhh[d * G_ + H_ + j];
    float bN = bhh[d * G_ + 2 * H_ + j];
    __syncthreads();

    for (int s = 0; s < T_; s++) {
        int t = (d == 0) ? s : (T_ - 1 - s);
        if (LAYER == 0) {
            if (j < MB) tok_s[j] = inputs[(size_t)(b0 + j) * T_ + t];
        }
        __syncthreads();

        float xr[MB], xz[MB], xn[MB];
#pragma unroll
        for (int m = 0; m < MB; m++) {
            const float* xp = (LAYER == 0)
                ? &g_embproj[d][tok_s[m]][0]
                : &g_xp1[d][(size_t)t * B_ + b0 + m][0];
            xr[m] = xp[j];
            xz[m] = xp[H_ + j];
            xn[m] = xp[2 * H_ + j];
        }

        float aR[MB], aZ[MB], aN[MB];
#pragma unroll
        for (int m = 0; m < MB; m++) { aR[m] = 0.f; aZ[m] = 0.f; aN[m] = 0.f; }

        const float* w = whhT;
        for (int k = 0; k < H_; k += 4) {
            float4 hv4[MB];
#pragma unroll
            for (int m = 0; m < MB; m++)
                hv4[m] = *reinterpret_cast<const float4*>(&h_s[m][k]);
#pragma unroll
            for (int kk = 0; kk < 4; kk++) {
                float wr = w[j];
                float wz = w[H_ + j];
                float wn = w[2 * H_ + j];
#pragma unroll
                for (int m = 0; m < MB; m++) {
                    float hv = reinterpret_cast<const float*>(&hv4[m])[kk];
                    aR[m] = fmaf(hv, wr, aR[m]);
                    aZ[m] = fmaf(hv, wz, aZ[m]);
                    aN[m] = fmaf(hv, wn, aN[m]);
                }
                w += G_;
            }
        }

        float hnew[MB];
#pragma unroll
        for (int m = 0; m < MB; m++) {
            float r = sigmoidf_(xr[m] + aR[m] + bR);
            float z = sigmoidf_(xz[m] + aZ[m] + bZ);
            float n = tanhf(xn[m] + r * (aN[m] + bN));
            hnew[m] = (1.0f - z) * n + z * h_s[m][j];
        }
        __syncthreads();

#pragma unroll
        for (int m = 0; m < MB; m++) {
            h_s[m][j] = hnew[m];
            if (LAYER == 0) {
                size_t idx = ((size_t)t * B_ + b0 + m) * 512 + d * H_ + j;
                __nv_bfloat16 hi, lo;
                split_bf16(hnew[m], hi, lo);
                g_h1hi[idx] = hi;
                g_h1lo[idx] = lo;
            } else {
                g_h2[t][b0 + m][d * H_ + j] = hnew[m];
            }
        }
    }
}

// ---------------- layer-1 input projection: mma.sync split-bf16 GEMM ----------------
// C[m,n] = sum_k A[m,k]*W[n,k]; M=131072, N=768 (x2 dir), K=512.
// CTA 128x128, BK=32, 8 warps (2m x 4n), warp 64x32.
// 3-term: Ahi*Bhi + Ahi*Blo + Alo*Bhi. cp.async double-buffered.
#define XPS_ROWB 80                    // smem row stride bytes (40 bf16)
#define XPS_BUF  10240                 // 128 rows * 80B
#define XPS_STG  40960                 // 4 buffers (Ahi,Alo,Bhi,Blo)
#define XPS_TOT  81920                 // 2 stages

__global__ void __launch_bounds__(256) k_xp1_mma(const float* __restrict__ bih1) {
    extern __shared__ char sm[];
    const uint32_t smb = smem_u32(sm);
    const int tid  = threadIdx.x;
    const int wid  = tid >> 5, lane = tid & 31;
    const int g    = lane >> 2;          // 0..7
    const int cc   = (lane & 3) * 2;     // 0,2,4,6
    const int d    = blockIdx.x / 6;
    const int n0   = (blockIdx.x % 6) * 128;
    const int m0   = blockIdx.y * 128;
    const int wm   = wid >> 2;           // 0..1
    const int wn   = wid & 3;            // 0..3

    const __nv_bfloat16* Ahi = g_h1hi;
    const __nv_bfloat16* Alo = g_h1lo;
    const __nv_bfloat16* Bhi = g_wih1hi + (size_t)d * G_ * 512;
    const __nv_bfloat16* Blo = g_wih1lo + (size_t)d * G_ * 512;

    float C[4][4][4];
#pragma unroll
    for (int mf = 0; mf < 4; mf++)
#pragma unroll
        for (int nf = 0; nf < 4; nf++)
#pragma unroll
            for (int q = 0; q < 4; q++) C[mf][nf][q] = 0.f;

    // per-thread static load decomposition: i -> buf=i>>1, row=((i&1)<<6)+(tid>>2), u=tid&3
    const int lrow = tid >> 2, lu = tid & 3;

    auto issue_loads = [&](int kt, int stage) {
        int k0 = kt * 32;
        uint32_t sb = smb + stage * XPS_STG;
#pragma unroll
        for (int i = 0; i < 8; i++) {
            int buf = i >> 1;
            int row = ((i & 1) << 6) + lrow;
            const __nv_bfloat16* gp;
            if (buf == 0)      gp = Ahi + (size_t)(m0 + row) * 512 + k0 + lu * 8;
            else if (buf == 1) gp = Alo + (size_t)(m0 + row) * 512 + k0 + lu * 8;
            else if (buf == 2) gp = Bhi + (size_t)(n0 + row) * 512 + k0 + lu * 8;
            else               gp = Blo + (size_t)(n0 + row) * 512 + k0 + lu * 8;
            uint32_t sa = sb + buf * XPS_BUF + row * XPS_ROWB + lu * 16;
            asm volatile("cp.async.cg.shared.global [%0], [%1], 16;" :: "r"(sa), "l"(gp));
        }
        asm volatile("cp.async.commit_group;");
    };

    issue_loads(0, 0);

    for (int kt = 0; kt < 16; kt++) {
        if (kt + 1 < 16) issue_loads(kt + 1, (kt + 1) & 1);
        else             asm volatile("cp.async.commit_group;");
        asm volatile("cp.async.wait_group 1;");
        __syncthreads();

        const char* base = sm + (kt & 1) * XPS_STG;
        const char* SAh = base;
        const char* SAl = base + XPS_BUF;
        const char* SBh = base + 2 * XPS_BUF;
        const char* SBl = base + 3 * XPS_BUF;

#pragma unroll
        for (int ks = 0; ks < 2; ks++) {
            int kb = ks * 16;
            uint32_t ah[4][4], al[4][4], bh[4][2], bl[4][2];
#pragma unroll
            for (int mf = 0; mf < 4; mf++) {
                int mrow = wm * 64 + mf * 16 + g;
                size_t o0 = (size_t)mrow * XPS_ROWB + (kb + cc) * 2;
                size_t o1 = (size_t)(mrow + 8) * XPS_ROWB + (kb + cc) * 2;
                ah[mf][0] = *(const uint32_t*)(SAh + o0);
                ah[mf][1] = *(const uint32_t*)(SAh + o1);
                ah[mf][2] = *(const uint32_t*)(SAh + o0 + 16);
                ah[mf][3] = *(const uint32_t*)(SAh + o1 + 16);
                al[mf][0] = *(const uint32_t*)(SAl + o0);
                al[mf][1] = *(const uint32_t*)(SAl + o1);
                al[mf][2] = *(const uint32_t*)(SAl + o0 + 16);
                al[mf][3] = *(const uint32_t*)(SAl + o1 + 16);
            }
#pragma unroll
            for (int nf = 0; nf < 4; nf++) {
                int nrow = wn * 32 + nf * 8 + g;
                size_t o0 = (size_t)nrow * XPS_ROWB + (kb + cc) * 2;
                bh[nf][0] = *(const uint32_t*)(SBh + o0);
                bh[nf][1] = *(const uint32_t*)(SBh + o0 + 16);
                bl[nf][0] = *(const uint32_t*)(SBl + o0);
                bl[nf][1] = *(const uint32_t*)(SBl + o0 + 16);
            }
#pragma unroll
            for (int mf = 0; mf < 4; mf++)
#pragma unroll
                for (int nf = 0; nf < 4; nf++) {
                    mma_bf16(C[mf][nf], ah[mf], bh[nf]);
                    mma_bf16(C[mf][nf], ah[mf], bl[nf]);
                    mma_bf16(C[mf][nf], al[mf], bh[nf]);
                }
        }
        __syncthreads();
    }

    // epilogue: add bias, store fp32
    float bias[8];
#pragma unroll
    for (int nf = 0; nf < 4; nf++) {
        int col = n0 + wn * 32 + nf * 8 + cc;
        bias[nf * 2 + 0] = __ldg(bih1 + d * G_ + col);
        bias[nf * 2 + 1] = __ldg(bih1 + d * G_ + col + 1);
    }
#pragma unroll
    for (int mf = 0; mf < 4; mf++) {
        int row = m0 + wm * 64 + mf * 16 + g;
#pragma unroll
        for (int nf = 0; nf < 4; nf++) {
            int col = n0 + wn * 32 + nf * 8 + cc;
            float2 v0 = make_float2(C[mf][nf][0] + bias[nf * 2],
                                    C[mf][nf][1] + bias[nf * 2 + 1]);
            float2 v1 = make_float2(C[mf][nf][2] + bias[nf * 2],
                                    C[mf][nf][3] + bias[nf * 2 + 1]);
            *reinterpret_cast<float2*>(&g_xp1[d][(size_t)row][col]) = v0;
            *reinterpret_cast<float2*>(&g_xp1[d][(size_t)row + 8][col]) = v1;
        }
    }
}

// ---------------- FC1: C[256,128] over K=262144, K-split ----------
__global__ void k_fc1(const float* __restrict__ W1) {
    const int BK = 16, CH = 262144 / KC_;
    int kc = blockIdx.x;
    int b0 = blockIdx.y * 128;

    __shared__ float As[BK][129];
    __shared__ float Bs[BK][129];

    int tid = threadIdx.x;
    int tbi = tid & 15;
    int tji = tid >> 4;

    const float* h2 = &g_h2[0][0][0];

    float acc[8][8];
#pragma unroll
    for (int i = 0; i < 8; i++)
#pragma unroll
        for (int jj = 0; jj < 8; jj++) acc[i][jj] = 0.f;

    for (int kk = 0; kk < CH; kk += BK) {
        int kbase = kc * CH + kk;
        int t  = kbase >> 9;
        int c0 = kbase & 511;
#pragma unroll
        for (int i = 0; i < 8; i++) {
            int idx = tid + i * 256;
            int b = idx >> 4, k = idx & 15;
            As[k][b] = h2[((size_t)t * B_ + b0 + b) * 512 + c0 + k];
        }
#pragma unroll
        for (int i = 0; i < 8; i++) {
            int idx = tid + i * 256;
            int j = idx >> 4, k = idx & 15;
            Bs[k][j] = W1[(size_t)j * 262144 + kbase + k];
        }
        __syncthreads();
#pragma unroll
        for (int k = 0; k < BK; k++) {
            float ra[8], rb[8];
#pragma unroll
            for (int i = 0; i < 8; i++) ra[i] = As[k][tbi + 16 * i];
#pragma unroll
            for (int jj = 0; jj < 8; jj++) rb[jj] = Bs[k][tji + 16 * jj];
#pragma unroll
            for (int i = 0; i < 8; i++)
#pragma unroll
                for (int jj = 0; jj < 8; jj++) acc[i][jj] = fmaf(ra[i], rb[jj], acc[i][jj]);
        }
        __syncthreads();
    }
#pragma unroll
    for (int i = 0; i < 8; i++)
#pragma unroll
        for (int jj = 0; jj < 8; jj++)
            g_fc1p[kc][b0 + tbi + 16 * i][tji + 16 * jj] = acc[i][jj];
}

__global__ void k_fc1reduce(const float* __restrict__ b1) {
    int idx = blockIdx.x * 256 + threadIdx.x;
    int b = idx >> 7, jj = idx & 127;
    float s = b1[jj];
#pragma unroll 8
    for (int kc = 0; kc < KC_; kc++) s += g_fc1p[kc][b][jj];
    g_fc1[b][jj] = (s > 0.f) ? s : 0.01f * s;
}

__global__ void k_fc2(const float* __restrict__ W2, const float* __restrict__ b2,
                      float* __restrict__ out) {
    int b = threadIdx.x;
    float s = b2[0];
#pragma unroll 8
    for (int j = 0; j < 128; j++) s = fmaf(g_fc1[b][j], W2[j], s);
    out[b] = 1.0f / (1.0f + expf(-s));
}

// ---------------- launch ----------------
extern "C" void kernel_launch(void* const* d_in, const int* in_sizes, int n_in,
                              void* d_out, int out_size) {
    const int*   inputs  = (const int*)  d_in[0];
    const float* emb     = (const float*)d_in[1];
    const float* w_ih_l0 = (const float*)d_in[2];
    const float* w_hh_l0 = (const float*)d_in[3];
    const float* b_ih_l0 = (const float*)d_in[4];
    const float* b_hh_l0 = (const float*)d_in[5];
    const float* w_ih_l1 = (const float*)d_in[6];
    const float* w_hh_l1 = (const float*)d_in[7];
    const float* b_ih_l1 = (const float*)d_in[8];
    const float* b_hh_l1 = (const float*)d_in[9];
    const float* W1      = (const float*)d_in[10];
    const float* b1      = (const float*)d_in[11];
    const float* W2      = (const float*)d_in[12];
    const float* b2      = (const float*)d_in[13];
    float* out = (float*)d_out;

    cudaFuncSetAttribute(k_xp1_mma, cudaFuncAttributeMaxDynamicSharedMemorySize, XPS_TOT);

    k_embproj<<<2 * V1, G_>>>(emb, w_ih_l0, b_ih_l0);
    k_transpose<<<256, 256>>>(w_hh_l0, 0);
    k_transpose<<<256, 256>>>(w_hh_l1, 1);
    k_split_wih1<<<3072, 256>>>(w_ih_l1);

    k_rec<0><<<2 * (B_ / MB), 256>>>(inputs, b_hh_l0);

    k_xp1_mma<<<dim3(12, 1024), 256, XPS_TOT>>>(b_ih_l1);

    k_rec<1><<<2 * (B_ / MB), 256>>>(inputs, b_hh_l1);

    k_fc1<<<dim3(KC_, 2), 256>>>(W1);
    k_fc1reduce<<<128, 256>>>(b1);
    k_fc2<<<1, 256>>>(W2, b2, out);
}

// round 8
// speedup vs baseline: 1.7660x; 1.5380x over previous
#include <cuda_runtime.h>
#include <cuda_bf16.h>
#include <math.h>
#include <stdint.h>

#define B_  256
#define T_  512
#define E_  128
#define H_  256
#define G_  768   // 3*H
#define V1  65
#define MB  4     // batch rows per recurrence CTA
#define KC_ 64    // FC1 K-split chunks

// ---------------- scratch (static device globals; no allocation) ----------------
__device__ float g_embproj[2][V1][G_];
__device__ float g_whh0T[2][H_][G_];
__device__ float g_whh1T[2][H_][G_];
__device__ __align__(16) __nv_bfloat16 g_h1hi[(size_t)T_ * B_ * 512];
__device__ __align__(16) __nv_bfloat16 g_h1lo[(size_t)T_ * B_ * 512];
__device__ __align__(16) __nv_bfloat16 g_wih1hi[2 * G_ * 512];
__device__ __align__(16) __nv_bfloat16 g_wih1lo[2 * G_ * 512];
__device__ float g_xp1[2][(size_t)T_ * B_][G_];
__device__ float g_h2[T_][B_][2 * H_];
__device__ float g_fc1p[KC_][B_][128];
__device__ float g_fc1[B_][128];

__device__ __forceinline__ uint32_t smem_u32(const void* p) {
    uint32_t a;
    asm("{ .reg .u64 t; cvta.to.shared.u64 t, %1; cvt.u32.u64 %0, t; }" : "=r"(a) : "l"(p));
    return a;
}
__device__ __forceinline__ void split_bf16(float x, __nv_bfloat16& hi, __nv_bfloat16& lo) {
    hi = __float2bfloat16_rn(x);
    lo = __float2bfloat16_rn(x - __bfloat162float(hi));
}
__device__ __forceinline__ void mma_bf16(float* c, const uint32_t* a, const uint32_t* b) {
    asm volatile(
        "mma.sync.aligned.m16n8k16.row.col.f32.bf16.bf16.f32 "
        "{%0,%1,%2,%3}, {%4,%5,%6,%7}, {%8,%9}, {%0,%1,%2,%3};"
        : "+f"(c[0]), "+f"(c[1]), "+f"(c[2]), "+f"(c[3])
        : "r"(a[0]), "r"(a[1]), "r"(a[2]), "r"(a[3]), "r"(b[0]), "r"(b[1]));
}

// ---------------- prep: embedding projection for layer 0 ----------------
__global__ void k_embproj(const float* __restrict__ emb,
                          const float* __restrict__ w_ih0,
                          const float* __restrict__ b_ih0) {
    __shared__ float es[E_];
    int d = blockIdx.x / V1;
    int v = blockIdx.x % V1;
    int g = threadIdx.x;
    if (g < E_) es[g] = emb[v * E_ + g];
    __syncthreads();
    const float* w = w_ih0 + ((size_t)d * G_ + g) * E_;
    float acc = b_ih0[d * G_ + g];
#pragma unroll 4
    for (int e = 0; e < E_; e++) acc = fmaf(es[e], w[e], acc);
    g_embproj[d][v][g] = acc;
}

// ---------------- prep: w_hh transposes [2][G][H] -> [2][H][G] ----------------
__global__ void k_transpose(const float* __restrict__ in, int which) {
    float* out = (which == 0) ? &g_whh0T[0][0][0] : &g_whh1T[0][0][0];
    size_t total = (size_t)2 * G_ * H_;
    for (size_t i = (size_t)blockIdx.x * blockDim.x + threadIdx.x; i < total;
         i += (size_t)gridDim.x * blockDim.x) {
        int k = (int)(i % H_);
        size_t r = i / H_;
        int g = (int)(r % G_);
        int d = (int)(r / G_);
        out[((size_t)d * H_ + k) * G_ + g] = in[i];
    }
}

// ---------------- prep: split w_ih_l1 into bf16 hi/lo ----------------
__global__ void k_split_wih1(const float* __restrict__ w) {
    int i = blockIdx.x * 256 + threadIdx.x;
    float x = w[i];
    __nv_bfloat16 hi, lo;
    split_bf16(x, hi, lo);
    g_wih1hi[i] = hi;
    g_wih1lo[i] = lo;
}

__device__ __forceinline__ float sigmoidf_(float x) { return 1.0f / (1.0f + expf(-x)); }

// ---------------- GRU recurrence: 768 threads, gate-row parallel ----------------
// Thread g owns gate output g (0..767) for MB batch rows.
// Phase A: acc[m] = sum_k h[m][k] * whhT[k][g] (coalesced w stream, 1 LDG/k).
// Exchange via smem gbuf (stride-5 pad, conflict-free), Phase B: 256 threads
// apply nonlinearities and update h.
template <int LAYER>
__global__ void __launch_bounds__(768) k_rec(const int* __restrict__ inputs,
                                             const float* __restrict__ bhh) {
    const int nb = B_ / MB;                 // 64
    int d  = blockIdx.x / nb;
    int b0 = (blockIdx.x % nb) * MB;
    int g  = threadIdx.x;                   // 0..767

    __shared__ __align__(16) float h_s[MB][H_];
    __shared__ float gbuf[G_ * 5];          // [g][m] stride 5
    __shared__ float xnbuf[H_ * 5];         // xn for phase B
    __shared__ int   tok_s[MB][T_];         // all tokens, loaded once

    if (g < H_) {
#pragma unroll
        for (int m = 0; m < MB; m++) h_s[m][g] = 0.0f;
    }
    if (LAYER == 0) {
        for (int i = g; i < MB * T_; i += 768)
            tok_s[i / T_][i % T_] = inputs[(size_t)(b0 + i / T_) * T_ + (i % T_)];
    }

    const float* whhT = (LAYER == 0) ? &g_whh0T[d][0][0] : &g_whh1T[d][0][0];
    const float bg = bhh[d * G_ + g];
    const bool is_n = (g >= 2 * H_);
    __syncthreads();

    for (int s = 0; s < T_; s++) {
        int t = (d == 0) ? s : (T_ - 1 - s);

        // x-side projections (issued early; coalesced across g)
        float xg[MB];
#pragma unroll
        for (int m = 0; m < MB; m++) {
            const float* xp = (LAYER == 0)
                ? &g_embproj[d][tok_s[m][t]][0]
                : &g_xp1[d][(size_t)t * B_ + b0 + m][0];
            xg[m] = __ldg(xp + g);
        }

        float acc[MB];
#pragma unroll
        for (int m = 0; m < MB; m++) acc[m] = 0.f;

        const float* w = whhT + g;
#pragma unroll 2
        for (int k = 0; k < H_; k += 4) {
            float4 h4[MB];
#pragma unroll
            for (int m = 0; m < MB; m++)
                h4[m] = *reinterpret_cast<const float4*>(&h_s[m][k]);
            float w0 = w[0];
            float w1 = w[G_];
            float w2 = w[2 * G_];
            float w3 = w[3 * G_];
#pragma unroll
            for (int m = 0; m < MB; m++) {
                acc[m] = fmaf(h4[m].x, w0, acc[m]);
                acc[m] = fmaf(h4[m].y, w1, acc[m]);
                acc[m] = fmaf(h4[m].z, w2, acc[m]);
                acc[m] = fmaf(h4[m].w, w3, acc[m]);
            }
            w += 4 * G_;
        }

        // store gate partials (r,z: fold x-side; n: keep hh-side separate)
        if (!is_n) {
#pragma unroll
            for (int m = 0; m < MB; m++) gbuf[g * 5 + m] = acc[m] + bg + xg[m];
        } else {
#pragma unroll
            for (int m = 0; m < MB; m++) {
                gbuf[g * 5 + m] = acc[m] + bg;
                xnbuf[(g - 2 * H_) * 5 + m] = xg[m];
            }
        }
        __syncthreads();   // gbuf ready; all h_s reads done

        if (g < H_) {
            int j = g;
            float hnew[MB];
#pragma unroll
            for (int m = 0; m < MB; m++) {
                float r = sigmoidf_(gbuf[j * 5 + m]);
                float z = sigmoidf_(gbuf[(H_ + j) * 5 + m]);
                float n = tanhf(xnbuf[j * 5 + m] + r * gbuf[(2 * H_ + j) * 5 + m]);
                hnew[m] = (1.0f - z) * n + z * h_s[m][j];
            }
#pragma unroll
            for (int m = 0; m < MB; m++) {
                h_s[m][j] = hnew[m];
                if (LAYER == 0) {
                    size_t idx = ((size_t)t * B_ + b0 + m) * 512 + d * H_ + j;
                    __nv_bfloat16 hi, lo;
                    split_bf16(hnew[m], hi, lo);
                    g_h1hi[idx] = hi;
                    g_h1lo[idx] = lo;
                } else {
                    g_h2[t][b0 + m][d * H_ + j] = hnew[m];
                }
            }
        }
        __syncthreads();   // h_s updated for next step
    }
}

// ---------------- layer-1 input projection: mma.sync split-bf16 GEMM ----------------
#define XPS_ROWB 80
#define XPS_BUF  10240
#define XPS_STG  40960
#define XPS_TOT  81920

__global__ void __launch_bounds__(256) k_xp1_mma(const float* __restrict__ bih1) {
    extern __shared__ char sm[];
    const uint32_t smb = smem_u32(sm);
    const int tid  = threadIdx.x;
    const int wid  = tid >> 5, lane = tid & 31;
    const int g    = lane >> 2;
    const int cc   = (lane & 3) * 2;
    const int d    = blockIdx.x / 6;
    const int n0   = (blockIdx.x % 6) * 128;
    const int m0   = blockIdx.y * 128;
    const int wm   = wid >> 2;
    const int wn   = wid & 3;

    const __nv_bfloat16* Ahi = g_h1hi;
    const __nv_bfloat16* Alo = g_h1lo;
    const __nv_bfloat16* Bhi = g_wih1hi + (size_t)d * G_ * 512;
    const __nv_bfloat16* Blo = g_wih1lo + (size_t)d * G_ * 512;

    float C[4][4][4];
#pragma unroll
    for (int mf = 0; mf < 4; mf++)
#pragma unroll
        for (int nf = 0; nf < 4; nf++)
#pragma unroll
            for (int q = 0; q < 4; q++) C[mf][nf][q] = 0.f;

    const int lrow = tid >> 2, lu = tid & 3;

    auto issue_loads = [&](int kt, int stage) {
        int k0 = kt * 32;
        uint32_t sb = smb + stage * XPS_STG;
#pragma unroll
        for (int i = 0; i < 8; i++) {
            int buf = i >> 1;
            int row = ((i & 1) << 6) + lrow;
            const __nv_bfloat16* gp;
            if (buf == 0)      gp = Ahi + (size_t)(m0 + row) * 512 + k0 + lu * 8;
            else if (buf == 1) gp = Alo + (size_t)(m0 + row) * 512 + k0 + lu * 8;
            else if (buf == 2) gp = Bhi + (size_t)(n0 + row) * 512 + k0 + lu * 8;
            else               gp = Blo + (size_t)(n0 + row) * 512 + k0 + lu * 8;
            uint32_t sa = sb + buf * XPS_BUF + row * XPS_ROWB + lu * 16;
            asm volatile("cp.async.cg.shared.global [%0], [%1], 16;" :: "r"(sa), "l"(gp));
        }
        asm volatile("cp.async.commit_group;");
    };

    issue_loads(0, 0);

    for (int kt = 0; kt < 16; kt++) {
        if (kt + 1 < 16) issue_loads(kt + 1, (kt + 1) & 1);
        else             asm volatile("cp.async.commit_group;");
        asm volatile("cp.async.wait_group 1;");
        __syncthreads();

        const char* base = sm + (kt & 1) * XPS_STG;
        const char* SAh = base;
        const char* SAl = base + XPS_BUF;
        const char* SBh = base + 2 * XPS_BUF;
        const char* SBl = base + 3 * XPS_BUF;

#pragma unroll
        for (int ks = 0; ks < 2; ks++) {
            int kb = ks * 16;
            uint32_t ah[4][4], al[4][4], bh[4][2], bl[4][2];
#pragma unroll
            for (int mf = 0; mf < 4; mf++) {
                int mrow = wm * 64 + mf * 16 + g;
                size_t o0 = (size_t)mrow * XPS_ROWB + (kb + cc) * 2;
                size_t o1 = (size_t)(mrow + 8) * XPS_ROWB + (kb + cc) * 2;
                ah[mf][0] = *(const uint32_t*)(SAh + o0);
                ah[mf][1] = *(const uint32_t*)(SAh + o1);
                ah[mf][2] = *(const uint32_t*)(SAh + o0 + 16);
                ah[mf][3] = *(const uint32_t*)(SAh + o1 + 16);
                al[mf][0] = *(const uint32_t*)(SAl + o0);
                al[mf][1] = *(const uint32_t*)(SAl + o1);
                al[mf][2] = *(const uint32_t*)(SAl + o0 + 16);
                al[mf][3] = *(const uint32_t*)(SAl + o1 + 16);
            }
#pragma unroll
            for (int nf = 0; nf < 4; nf++) {
                int nrow = wn * 32 + nf * 8 + g;
                size_t o0 = (size_t)nrow * XPS_ROWB + (kb + cc) * 2;
                bh[nf][0] = *(const uint32_t*)(SBh + o0);
                bh[nf][1] = *(const uint32_t*)(SBh + o0 + 16);
                bl[nf][0] = *(const uint32_t*)(SBl + o0);
                bl[nf][1] = *(const uint32_t*)(SBl + o0 + 16);
            }
#pragma unroll
            for (int mf = 0; mf < 4; mf++)
#pragma unroll
                for (int nf = 0; nf < 4; nf++) {
                    mma_bf16(C[mf][nf], ah[mf], bh[nf]);
                    mma_bf16(C[mf][nf], ah[mf], bl[nf]);
                    mma_bf16(C[mf][nf], al[mf], bh[nf]);
                }
        }
        __syncthreads();
    }

    float bias[8];
#pragma unroll
    for (int nf = 0; nf < 4; nf++) {
        int col = n0 + wn * 32 + nf * 8 + cc;
        bias[nf * 2 + 0] = __ldg(bih1 + d * G_ + col);
        bias[nf * 2 + 1] = __ldg(bih1 + d * G_ + col + 1);
    }
#pragma unroll
    for (int mf = 0; mf < 4; mf++) {
        int row = m0 + wm * 64 + mf * 16 + g;
#pragma unroll
        for (int nf = 0; nf < 4; nf++) {
            int col = n0 + wn * 32 + nf * 8 + cc;
            float2 v0 = make_float2(C[mf][nf][0] + bias[nf * 2],
                                    C[mf][nf][1] + bias[nf * 2 + 1]);
            float2 v1 = make_float2(C[mf][nf][2] + bias[nf * 2],
                                    C[mf][nf][3] + bias[nf * 2 + 1]);
            *reinterpret_cast<float2*>(&g_xp1[d][(size_t)row][col]) = v0;
            *reinterpret_cast<float2*>(&g_xp1[d][(size_t)row + 8][col]) = v1;
        }
    }
}

// ---------------- FC1 ----------
__global__ void k_fc1(const float* __restrict__ W1) {
    const int BK = 16, CH = 262144 / KC_;
    int kc = blockIdx.x;
    int b0 = blockIdx.y * 128;

    __shared__ float As[BK][129];
    __shared__ float Bs[BK][129];

    int tid = threadIdx.x;
    int tbi = tid & 15;
    int tji = tid >> 4;

    const float* h2 = &g_h2[0][0][0];

    float acc[8][8];
#pragma unroll
    for (int i = 0; i < 8; i++)
#pragma unroll
        for (int jj = 0; jj < 8; jj++) acc[i][jj] = 0.f;

    for (int kk = 0; kk < CH; kk += BK) {
        int kbase = kc * CH + kk;
        int t  = kbase >> 9;
        int c0 = kbase & 511;
#pragma unroll
        for (int i = 0; i < 8; i++) {
            int idx = tid + i * 256;
            int b = idx >> 4, k = idx & 15;
            As[k][b] = h2[((size_t)t * B_ + b0 + b) * 512 + c0 + k];
        }
#pragma unroll
        for (int i = 0; i < 8; i++) {
            int idx = tid + i * 256;
            int j = idx >> 4, k = idx & 15;
            Bs[k][j] = W1[(size_t)j * 262144 + kbase + k];
        }
        __syncthreads();
#pragma unroll
        for (int k = 0; k < BK; k++) {
            float ra[8], rb[8];
#pragma unroll
            for (int i = 0; i < 8; i++) ra[i] = As[k][tbi + 16 * i];
#pragma unroll
            for (int jj = 0; jj < 8; jj++) rb[jj] = Bs[k][tji + 16 * jj];
#pragma unroll
            for (int i = 0; i < 8; i++)
#pragma unroll
                for (int jj = 0; jj < 8; jj++) acc[i][jj] = fmaf(ra[i], rb[jj], acc[i][jj]);
        }
        __syncthreads();
    }
#pragma unroll
    for (int i = 0; i < 8; i++)
#pragma unroll
        for (int jj = 0; jj < 8; jj++)
            g_fc1p[kc][b0 + tbi + 16 * i][tji + 16 * jj] = acc[i][jj];
}

__global__ void k_fc1reduce(const float* __restrict__ b1) {
    int idx = blockIdx.x * 256 + threadIdx.x;
    int b = idx >> 7, jj = idx & 127;
    float s = b1[jj];
#pragma unroll 8
    for (int kc = 0; kc < KC_; kc++) s += g_fc1p[kc][b][jj];
    g_fc1[b][jj] = (s > 0.f) ? s : 0.01f * s;
}

__global__ void k_fc2(const float* __restrict__ W2, const float* __restrict__ b2,
                      float* __restrict__ out) {
    int b = threadIdx.x;
    float s = b2[0];
#pragma unroll 8
    for (int j = 0; j < 128; j++) s = fmaf(g_fc1[b][j], W2[j], s);
    out[b] = 1.0f / (1.0f + expf(-s));
}

// ---------------- launch ----------------
extern "C" void kernel_launch(void* const* d_in, const int* in_sizes, int n_in,
                              void* d_out, int out_size) {
    const int*   inputs  = (const int*)  d_in[0];
    const float* emb     = (const float*)d_in[1];
    const float* w_ih_l0 = (const float*)d_in[2];
    const float* w_hh_l0 = (const float*)d_in[3];
    const float* b_ih_l0 = (const float*)d_in[4];
    const float* b_hh_l0 = (const float*)d_in[5];
    const float* w_ih_l1 = (const float*)d_in[6];
    const float* w_hh_l1 = (const float*)d_in[7];
    const float* b_ih_l1 = (const float*)d_in[8];
    const float* b_hh_l1 = (const float*)d_in[9];
    const float* W1      = (const float*)d_in[10];
    const float* b1      = (const float*)d_in[11];
    const float* W2      = (const float*)d_in[12];
    const float* b2      = (const float*)d_in[13];
    float* out = (float*)d_out;

    cudaFuncSetAttribute(k_xp1_mma, cudaFuncAttributeMaxDynamicSharedMemorySize, XPS_TOT);

    k_embproj<<<2 * V1, G_>>>(emb, w_ih_l0, b_ih_l0);
    k_transpose<<<256, 256>>>(w_hh_l0, 0);
    k_transpose<<<256, 256>>>(w_hh_l1, 1);
    k_split_wih1<<<3072, 256>>>(w_ih_l1);

    k_rec<0><<<2 * (B_ / MB), 768>>>(inputs, b_hh_l0);

    k_xp1_mma<<<dim3(12, 1024), 256, XPS_TOT>>>(b_ih_l1);

    k_rec<1><<<2 * (B_ / MB), 768>>>(inputs, b_hh_l1);

    k_fc1<<<dim3(KC_, 2), 256>>>(W1);
    k_fc1reduce<<<128, 256>>>(b1);
    k_fc2<<<1, 256>>>(W2, b2, out);
}